// round 2
// baseline (speedup 1.0000x reference)
#include <cuda_runtime.h>
#include <cuda_bf16.h>
#include <math.h>

#define N_NODES 100000
#define F_IN    1433
#define F_H     32
#define F_OUT   7
#define E_MAX   3200000

// ---------------- scratch (static device globals; no allocation) ----------------
__device__ float g_deg [N_NODES];
__device__ float g_dinv[N_NODES];
__device__ float g_h   [N_NODES * F_H];   // x @ W1
__device__ float g_agg1[N_NODES * F_H];   // scatter accumulator layer 1
__device__ float g_h2  [N_NODES * 8];     // h1 @ W2, padded 7->8
__device__ float g_agg2[N_NODES * 8];     // scatter accumulator layer 2

// vector atomic add (sm_90+)
__device__ __forceinline__ void red_add_v4(float4* addr, float4 v) {
    asm volatile("red.global.add.v4.f32 [%0], {%1, %2, %3, %4};"
                 :: "l"((float*)addr), "f"(v.x), "f"(v.y), "f"(v.z), "f"(v.w) : "memory");
}

// ---------------- init: zero accumulators, deg=1 (self loop) ----------------
__global__ void init_kernel() {
    int idx = blockIdx.x * blockDim.x + threadIdx.x;
    // agg1: N*32 floats = 800000 float4
    if (idx < N_NODES * F_H / 4)
        ((float4*)g_agg1)[idx] = make_float4(0.f, 0.f, 0.f, 0.f);
    if (idx < N_NODES * 8 / 4)
        ((float4*)g_agg2)[idx] = make_float4(0.f, 0.f, 0.f, 0.f);
    if (idx < N_NODES)
        g_deg[idx] = 1.0f;   // self-loop contributes 1 to degree
}

// ---------------- degree ----------------
__global__ void deg_kernel(const int* __restrict__ dst, int E) {
    int e = blockIdx.x * blockDim.x + threadIdx.x;
    if (e < E) atomicAdd(&g_deg[dst[e]], 1.0f);
}

__global__ void dinv_kernel() {
    int i = blockIdx.x * blockDim.x + threadIdx.x;
    if (i < N_NODES) g_dinv[i] = rsqrtf(g_deg[i]);   // deg >= 1 always
}

// ---------------- GEMM1: h = x @ W1   (M=100000, N=32, K=1433) ----------------
#define BM 128
#define BK 32

__global__ __launch_bounds__(128, 8) void gemm1_kernel(
    const float* __restrict__ x, const float* __restrict__ W1)
{
    __shared__ __align__(16) float Xs[BK][BM + 4];   // transposed tile
    __shared__ __align__(16) float Ws[BK][F_H];

    const int tid  = threadIdx.x;
    const int colg = tid & 7;     // 0..7  -> cols colg*4 .. +3
    const int rowg = tid >> 3;    // 0..15 -> rows rowg*8 .. +7
    const int row0 = blockIdx.x * BM;
    const int rowg8 = rowg * 8;

    float acc[8][4];
    #pragma unroll
    for (int r = 0; r < 8; ++r)
        #pragma unroll
        for (int c = 0; c < 4; ++c) acc[r][c] = 0.f;

    for (int k0 = 0; k0 < F_IN; k0 += BK) {
        // load X tile (coalesced along k), store transposed
        #pragma unroll
        for (int l = tid; l < BM * BK; l += 128) {
            int k = l & 31;
            int r = l >> 5;
            int grow = row0 + r;
            int gk = k0 + k;
            float v = 0.f;
            if (grow < N_NODES && gk < F_IN)
                v = x[(size_t)grow * F_IN + gk];
            Xs[k][r] = v;
        }
        // load W tile
        #pragma unroll
        for (int l = tid; l < BK * F_H; l += 128) {
            int kw = l >> 5;
            int j  = l & 31;
            float v = 0.f;
            if (k0 + kw < F_IN) v = W1[(k0 + kw) * F_H + j];
            Ws[kw][j] = v;
        }
        __syncthreads();

        #pragma unroll
        for (int k = 0; k < BK; ++k) {
            float4 b  = *(const float4*)&Ws[k][colg * 4];
            float4 a0 = *(const float4*)&Xs[k][rowg8];
            float4 a1 = *(const float4*)&Xs[k][rowg8 + 4];
            float a[8] = {a0.x, a0.y, a0.z, a0.w, a1.x, a1.y, a1.z, a1.w};
            float bb[4] = {b.x, b.y, b.z, b.w};
            #pragma unroll
            for (int r = 0; r < 8; ++r)
                #pragma unroll
                for (int c = 0; c < 4; ++c)
                    acc[r][c] += a[r] * bb[c];
        }
        __syncthreads();
    }

    #pragma unroll
    for (int r = 0; r < 8; ++r) {
        int grow = row0 + rowg8 + r;
        if (grow < N_NODES)
            *(float4*)&g_h[(size_t)grow * F_H + colg * 4] =
                make_float4(acc[r][0], acc[r][1], acc[r][2], acc[r][3]);
    }
}

// ---------------- scatter layer 1: agg1[dst] += h[src]*norm ----------------
__global__ __launch_bounds__(256) void scatter1_kernel(
    const int* __restrict__ src, const int* __restrict__ dst, int E)
{
    int e = blockIdx.x * blockDim.x + threadIdx.x;
    if (e >= E) return;
    int s = src[e];
    int d = dst[e];
    float w = g_dinv[s] * g_dinv[d];
    const float4* hs = (const float4*)(g_h + s * F_H);
    float4* ad = (float4*)(g_agg1 + d * F_H);
    #pragma unroll
    for (int i = 0; i < 8; ++i) {
        float4 v = hs[i];
        v.x *= w; v.y *= w; v.z *= w; v.w *= w;
        red_add_v4(&ad[i], v);
    }
}

// ---------------- node-wise: h1 = relu(agg1 + h*dinv^2 + b1); h2 = h1 @ W2 ----------------
__global__ __launch_bounds__(256) void node1_kernel(
    const float* __restrict__ b1, const float* __restrict__ W2)
{
    __shared__ float sW2[F_H * F_OUT];
    __shared__ float sb1[F_H];
    int tid = threadIdx.x;
    if (tid < F_H * F_OUT) sW2[tid] = W2[tid];
    if (tid < F_H)         sb1[tid] = b1[tid];
    __syncthreads();

    int i = blockIdx.x * blockDim.x + tid;
    if (i >= N_NODES) return;
    float self = g_dinv[i] * g_dinv[i];

    float o[F_OUT];
    #pragma unroll
    for (int c = 0; c < F_OUT; ++c) o[c] = 0.f;

    const float4* ag = (const float4*)(g_agg1 + i * F_H);
    const float4* hh = (const float4*)(g_h + i * F_H);
    #pragma unroll
    for (int q = 0; q < 8; ++q) {
        float4 a = ag[q];
        float4 h = hh[q];
        float hv[4];
        hv[0] = a.x + h.x * self + sb1[q * 4 + 0];
        hv[1] = a.y + h.y * self + sb1[q * 4 + 1];
        hv[2] = a.z + h.z * self + sb1[q * 4 + 2];
        hv[3] = a.w + h.w * self + sb1[q * 4 + 3];
        #pragma unroll
        for (int t = 0; t < 4; ++t) {
            float hr = fmaxf(hv[t], 0.f);
            int j = q * 4 + t;
            #pragma unroll
            for (int c = 0; c < F_OUT; ++c)
                o[c] += hr * sW2[j * F_OUT + c];
        }
    }
    float* out = g_h2 + i * 8;
    #pragma unroll
    for (int c = 0; c < F_OUT; ++c) out[c] = o[c];
    out[7] = 0.f;
}

// ---------------- scatter layer 2: agg2[dst] += h2[src]*norm ----------------
__global__ __launch_bounds__(256) void scatter2_kernel(
    const int* __restrict__ src, const int* __restrict__ dst, int E)
{
    int e = blockIdx.x * blockDim.x + threadIdx.x;
    if (e >= E) return;
    int s = src[e];
    int d = dst[e];
    float w = g_dinv[s] * g_dinv[d];
    const float4* hs = (const float4*)(g_h2 + s * 8);
    float4* ad = (float4*)(g_agg2 + d * 8);
    #pragma unroll
    for (int i = 0; i < 2; ++i) {
        float4 v = hs[i];
        v.x *= w; v.y *= w; v.z *= w; v.w *= w;
        red_add_v4(&ad[i], v);
    }
}

// ---------------- final: out = log_softmax(agg2 + h2*dinv^2 + b2) ----------------
__global__ __launch_bounds__(256) void final_kernel(
    const float* __restrict__ b2, float* __restrict__ out)
{
    int i = blockIdx.x * blockDim.x + threadIdx.x;
    if (i >= N_NODES) return;
    float self = g_dinv[i] * g_dinv[i];
    const float* ag = g_agg2 + i * 8;
    const float* h2 = g_h2 + i * 8;
    float v[F_OUT];
    float m = -1e30f;
    #pragma unroll
    for (int c = 0; c < F_OUT; ++c) {
        v[c] = ag[c] + h2[c] * self + b2[c];
        m = fmaxf(m, v[c]);
    }
    float s = 0.f;
    #pragma unroll
    for (int c = 0; c < F_OUT; ++c) s += expf(v[c] - m);
    float lse = m + logf(s);
    float* o = out + (size_t)i * F_OUT;
    #pragma unroll
    for (int c = 0; c < F_OUT; ++c) o[c] = v[c] - lse;
}

// ---------------- launch ----------------
extern "C" void kernel_launch(void* const* d_in, const int* in_sizes, int n_in,
                              void* d_out, int out_size)
{
    const float* x   = (const float*)d_in[0];
    const int*   ei  = (const int*)  d_in[1];
    const float* W1  = (const float*)d_in[2];
    const float* b1  = (const float*)d_in[3];
    const float* W2  = (const float*)d_in[4];
    const float* b2  = (const float*)d_in[5];
    float* out = (float*)d_out;

    const int E = in_sizes[1] / 2;
    const int* src = ei;
    const int* dst = ei + E;

    int nb_init = (N_NODES * F_H / 4 + 255) / 256;
    init_kernel<<<nb_init, 256>>>();

    int nb_e = (E + 255) / 256;
    deg_kernel<<<nb_e, 256>>>(dst, E);

    int nb_n = (N_NODES + 255) / 256;
    dinv_kernel<<<nb_n, 256>>>();

    int nb_g = (N_NODES + BM - 1) / BM;
    gemm1_kernel<<<nb_g, 128>>>(x, W1);

    scatter1_kernel<<<nb_e, 256>>>(src, dst, E);

    node1_kernel<<<nb_n, 256>>>(b1, W2);

    scatter2_kernel<<<nb_e, 256>>>(src, dst, E);

    final_kernel<<<nb_n, 256>>>(b2, out);
}

// round 4
// speedup vs baseline: 2.3786x; 2.3786x over previous
#include <cuda_runtime.h>
#include <cuda_bf16.h>
#include <math.h>

#define N_NODES 100000
#define F_IN    1433
#define F_H     32
#define F_OUT   7

// ---------------- scratch (static device globals; no allocation) ----------------
__device__ float g_deg [N_NODES];
__device__ float g_dinv[N_NODES];
__device__ float g_h   [N_NODES * F_H];   // x @ W1
__device__ float g_agg1[N_NODES * F_H];   // scatter accumulator layer 1
__device__ float g_h2  [N_NODES * 8];     // h1 @ W2, padded 7->8
__device__ float g_agg2[N_NODES * 8];     // scatter accumulator layer 2

// vector atomic add (sm_90+)
__device__ __forceinline__ void red_add_v4(float4* addr, float4 v) {
    asm volatile("red.global.add.v4.f32 [%0], {%1, %2, %3, %4};"
                 :: "l"((float*)addr), "f"(v.x), "f"(v.y), "f"(v.z), "f"(v.w) : "memory");
}

__device__ __forceinline__ unsigned f2tf32(float v) {
    unsigned r;
    asm("cvt.rna.tf32.f32 %0, %1;" : "=r"(r) : "f"(v));
    return r;
}

__device__ __forceinline__ void mma_tf32(float* d, const unsigned* a, const unsigned* b) {
    asm volatile(
        "mma.sync.aligned.m16n8k8.row.col.f32.tf32.tf32.f32 "
        "{%0,%1,%2,%3}, {%4,%5,%6,%7}, {%8,%9}, {%0,%1,%2,%3};"
        : "+f"(d[0]), "+f"(d[1]), "+f"(d[2]), "+f"(d[3])
        : "r"(a[0]), "r"(a[1]), "r"(a[2]), "r"(a[3]), "r"(b[0]), "r"(b[1]));
}

// 4-byte cp.async: only needs 4B alignment (x rows are 4B-aligned, stride 5732B)
__device__ __forceinline__ void cp_async4(void* smem_dst, const void* gsrc, int src_bytes) {
    unsigned saddr = (unsigned)__cvta_generic_to_shared(smem_dst);
    asm volatile("cp.async.ca.shared.global [%0], [%1], 4, %2;"
                 :: "r"(saddr), "l"(gsrc), "r"(src_bytes) : "memory");
}
// 16-byte cp.async for W (row stride 128B -> always 16B aligned)
__device__ __forceinline__ void cp_async16(void* smem_dst, const void* gsrc, int src_bytes) {
    unsigned saddr = (unsigned)__cvta_generic_to_shared(smem_dst);
    asm volatile("cp.async.cg.shared.global [%0], [%1], 16, %2;"
                 :: "r"(saddr), "l"(gsrc), "r"(src_bytes) : "memory");
}
__device__ __forceinline__ void cp_commit() { asm volatile("cp.async.commit_group;" ::: "memory"); }
__device__ __forceinline__ void cp_wait1()  { asm volatile("cp.async.wait_group 1;" ::: "memory"); }
__device__ __forceinline__ void cp_wait0()  { asm volatile("cp.async.wait_group 0;" ::: "memory"); }

// ---------------- init: zero accumulators, deg=1 (self loop) ----------------
__global__ void init_kernel() {
    int idx = blockIdx.x * blockDim.x + threadIdx.x;
    if (idx < N_NODES * F_H / 4)
        ((float4*)g_agg1)[idx] = make_float4(0.f, 0.f, 0.f, 0.f);
    if (idx < N_NODES * 8 / 4)
        ((float4*)g_agg2)[idx] = make_float4(0.f, 0.f, 0.f, 0.f);
    if (idx < N_NODES)
        g_deg[idx] = 1.0f;   // self-loop contributes 1 to degree
}

// ---------------- degree ----------------
__global__ void deg_kernel(const int* __restrict__ dst, int E) {
    int e = blockIdx.x * blockDim.x + threadIdx.x;
    if (e < E) atomicAdd(&g_deg[dst[e]], 1.0f);
}

__global__ void dinv_kernel() {
    int i = blockIdx.x * blockDim.x + threadIdx.x;
    if (i < N_NODES) g_dinv[i] = rsqrtf(g_deg[i]);
}

// ---------------- GEMM1 (tf32 tensor cores): h = x @ W1 ----------------
// M=100000, N=32, K=1433. Block: 128 threads (4 warps). BM=128 rows/block,
// each warp computes 32 rows x 32 cols with m16n8k8 tf32 MMA.
#define BM 128
#define BK 32
#define XPITCH 36
#define WPITCH 40
#define NCHUNK ((F_IN + BK - 1) / BK)   // 45

__global__ __launch_bounds__(128) void gemm1_kernel(
    const float* __restrict__ x, const float* __restrict__ W1)
{
    __shared__ __align__(16) float Xs[2][BM][XPITCH];
    __shared__ __align__(16) float Ws[2][BK][WPITCH];

    const int tid  = threadIdx.x;
    const int lane = tid & 31;
    const int warp = tid >> 5;
    const int gid  = lane >> 2;   // groupID   0..7
    const int tig  = lane & 3;    // thread-in-group 0..3
    const int row0 = blockIdx.x * BM;

    float acc[2][4][4];   // [mtile][ntile][reg]
    #pragma unroll
    for (int m = 0; m < 2; ++m)
        #pragma unroll
        for (int n = 0; n < 4; ++n)
            #pragma unroll
            for (int r = 0; r < 4; ++r) acc[m][n][r] = 0.f;

    auto issue_stage = [&](int chunk, int buf) {
        int k0 = chunk * BK;
        // X tile: 128 rows x 32 floats, 4B cp.async, 32 elems per thread.
        // lin = i*128 + tid -> r = lin>>5, c = lin&31 (coalesced within rows)
        #pragma unroll
        for (int i = 0; i < 32; ++i) {
            int lin = i * 128 + tid;
            int r = lin >> 5;
            int cc = lin & 31;
            int grow = row0 + r;
            int gcol = k0 + cc;
            const float* srcp = x;
            int valid = 0;
            if (grow < N_NODES && gcol < F_IN) {
                srcp = x + (size_t)grow * F_IN + gcol;
                valid = 4;
            }
            cp_async4(&Xs[buf][r][cc], srcp, valid);
        }
        // W tile: 32 rows x 32 floats = 256 x 16B chunks, 2 per thread
        #pragma unroll
        for (int i = 0; i < 2; ++i) {
            int lin = i * 128 + tid;
            int kw = lin >> 3;
            int j = lin & 7;
            int gk = k0 + kw;
            int valid = (gk < F_IN) ? 16 : 0;
            const float* srcp = W1 + (size_t)(valid ? gk : 0) * F_H + j * 4;
            cp_async16(&Ws[buf][kw][j * 4], srcp, valid);
        }
    };

    issue_stage(0, 0);
    cp_commit();

    for (int c = 0; c < NCHUNK; ++c) {
        int buf = c & 1;
        bool more = (c + 1 < NCHUNK);
        if (more) { issue_stage(c + 1, buf ^ 1); cp_commit(); }
        if (more) cp_wait1(); else cp_wait0();
        __syncthreads();

        const int wr = warp * 32;
        #pragma unroll
        for (int ks = 0; ks < 4; ++ks) {
            int kb = ks * 8;
            unsigned afr[2][4];
            #pragma unroll
            for (int m = 0; m < 2; ++m) {
                int rb = wr + m * 16;
                afr[m][0] = f2tf32(Xs[buf][rb + gid    ][kb + tig    ]);
                afr[m][1] = f2tf32(Xs[buf][rb + gid + 8][kb + tig    ]);
                afr[m][2] = f2tf32(Xs[buf][rb + gid    ][kb + tig + 4]);
                afr[m][3] = f2tf32(Xs[buf][rb + gid + 8][kb + tig + 4]);
            }
            #pragma unroll
            for (int n = 0; n < 4; ++n) {
                unsigned bfr[2];
                bfr[0] = f2tf32(Ws[buf][kb + tig    ][n * 8 + gid]);
                bfr[1] = f2tf32(Ws[buf][kb + tig + 4][n * 8 + gid]);
                mma_tf32(acc[0][n], afr[0], bfr);
                mma_tf32(acc[1][n], afr[1], bfr);
            }
        }
        __syncthreads();
    }

    // epilogue: d0=(r,2t), d1=(r,2t+1), d2=(r+8,2t), d3=(r+8,2t+1)
    #pragma unroll
    for (int m = 0; m < 2; ++m) {
        #pragma unroll
        for (int n = 0; n < 4; ++n) {
            int col = n * 8 + tig * 2;
            int r0r = row0 + warp * 32 + m * 16 + gid;
            if (r0r < N_NODES)
                *(float2*)&g_h[(size_t)r0r * F_H + col] =
                    make_float2(acc[m][n][0], acc[m][n][1]);
            int r1r = r0r + 8;
            if (r1r < N_NODES)
                *(float2*)&g_h[(size_t)r1r * F_H + col] =
                    make_float2(acc[m][n][2], acc[m][n][3]);
        }
    }
}

// ---------------- scatter layer 1: agg1[dst] += h[src]*norm ----------------
__global__ __launch_bounds__(256) void scatter1_kernel(
    const int* __restrict__ src, const int* __restrict__ dst, int E)
{
    int e = blockIdx.x * blockDim.x + threadIdx.x;
    if (e >= E) return;
    int s = src[e];
    int d = dst[e];
    float w = g_dinv[s] * g_dinv[d];
    const float4* hs = (const float4*)(g_h + s * F_H);
    float4* ad = (float4*)(g_agg1 + d * F_H);
    #pragma unroll
    for (int i = 0; i < 8; ++i) {
        float4 v = hs[i];
        v.x *= w; v.y *= w; v.z *= w; v.w *= w;
        red_add_v4(&ad[i], v);
    }
}

// ---------------- node-wise: h1 = relu(agg1 + h*dinv^2 + b1); h2 = h1 @ W2 ----------------
__global__ __launch_bounds__(256) void node1_kernel(
    const float* __restrict__ b1, const float* __restrict__ W2)
{
    __shared__ float sW2[F_H * F_OUT];
    __shared__ float sb1[F_H];
    int tid = threadIdx.x;
    if (tid < F_H * F_OUT) sW2[tid] = W2[tid];
    if (tid < F_H)         sb1[tid] = b1[tid];
    __syncthreads();

    int i = blockIdx.x * blockDim.x + tid;
    if (i >= N_NODES) return;
    float self = g_dinv[i] * g_dinv[i];

    float o[F_OUT];
    #pragma unroll
    for (int c = 0; c < F_OUT; ++c) o[c] = 0.f;

    const float4* ag = (const float4*)(g_agg1 + i * F_H);
    const float4* hh = (const float4*)(g_h + i * F_H);
    #pragma unroll
    for (int q = 0; q < 8; ++q) {
        float4 a = ag[q];
        float4 h = hh[q];
        float hv[4];
        hv[0] = a.x + h.x * self + sb1[q * 4 + 0];
        hv[1] = a.y + h.y * self + sb1[q * 4 + 1];
        hv[2] = a.z + h.z * self + sb1[q * 4 + 2];
        hv[3] = a.w + h.w * self + sb1[q * 4 + 3];
        #pragma unroll
        for (int t = 0; t < 4; ++t) {
            float hr = fmaxf(hv[t], 0.f);
            int j = q * 4 + t;
            #pragma unroll
            for (int c = 0; c < F_OUT; ++c)
                o[c] += hr * sW2[j * F_OUT + c];
        }
    }
    float* out = g_h2 + i * 8;
    #pragma unroll
    for (int c = 0; c < F_OUT; ++c) out[c] = o[c];
    out[7] = 0.f;
}

// ---------------- scatter layer 2: agg2[dst] += h2[src]*norm ----------------
__global__ __launch_bounds__(256) void scatter2_kernel(
    const int* __restrict__ src, const int* __restrict__ dst, int E)
{
    int e = blockIdx.x * blockDim.x + threadIdx.x;
    if (e >= E) return;
    int s = src[e];
    int d = dst[e];
    float w = g_dinv[s] * g_dinv[d];
    const float4* hs = (const float4*)(g_h2 + s * 8);
    float4* ad = (float4*)(g_agg2 + d * 8);
    #pragma unroll
    for (int i = 0; i < 2; ++i) {
        float4 v = hs[i];
        v.x *= w; v.y *= w; v.z *= w; v.w *= w;
        red_add_v4(&ad[i], v);
    }
}

// ---------------- final: out = log_softmax(agg2 + h2*dinv^2 + b2) ----------------
__global__ __launch_bounds__(256) void final_kernel(
    const float* __restrict__ b2, float* __restrict__ out)
{
    int i = blockIdx.x * blockDim.x + threadIdx.x;
    if (i >= N_NODES) return;
    float self = g_dinv[i] * g_dinv[i];
    const float* ag = g_agg2 + i * 8;
    const float* h2 = g_h2 + i * 8;
    float v[F_OUT];
    float m = -1e30f;
    #pragma unroll
    for (int c = 0; c < F_OUT; ++c) {
        v[c] = ag[c] + h2[c] * self + b2[c];
        m = fmaxf(m, v[c]);
    }
    float s = 0.f;
    #pragma unroll
    for (int c = 0; c < F_OUT; ++c) s += expf(v[c] - m);
    float lse = m + logf(s);
    float* o = out + (size_t)i * F_OUT;
    #pragma unroll
    for (int c = 0; c < F_OUT; ++c) o[c] = v[c] - lse;
}

// ---------------- launch ----------------
extern "C" void kernel_launch(void* const* d_in, const int* in_sizes, int n_in,
                              void* d_out, int out_size)
{
    const float* x   = (const float*)d_in[0];
    const int*   ei  = (const int*)  d_in[1];
    const float* W1  = (const float*)d_in[2];
    const float* b1  = (const float*)d_in[3];
    const float* W2  = (const float*)d_in[4];
    const float* b2  = (const float*)d_in[5];
    float* out = (float*)d_out;

    const int E = in_sizes[1] / 2;
    const int* src = ei;
    const int* dst = ei + E;

    int nb_init = (N_NODES * F_H / 4 + 255) / 256;
    init_kernel<<<nb_init, 256>>>();

    int nb_e = (E + 255) / 256;
    deg_kernel<<<nb_e, 256>>>(dst, E);

    int nb_n = (N_NODES + 255) / 256;
    dinv_kernel<<<nb_n, 256>>>();

    int nb_g = (N_NODES + BM - 1) / BM;
    gemm1_kernel<<<nb_g, 128>>>(x, W1);

    scatter1_kernel<<<nb_e, 256>>>(src, dst, E);

    node1_kernel<<<nb_n, 256>>>(b1, W2);

    scatter2_kernel<<<nb_e, 256>>>(src, dst, E);

    final_kernel<<<nb_n, 256>>>(b2, out);
}

// round 5
// speedup vs baseline: 3.8660x; 1.6253x over previous
#include <cuda_runtime.h>
#include <cuda_bf16.h>
#include <math.h>

#define N_NODES 100000
#define F_IN    1433
#define F_H     32
#define F_OUT   7

// ---------------- scratch (static device globals; no allocation) ----------------
__device__ float g_deg [N_NODES];
__device__ float g_dinv[N_NODES];
__device__ float g_h   [N_NODES * F_H];   // (x @ W1) * dinv[row]  (pre-scaled)
__device__ float g_agg1[N_NODES * F_H];   // scatter accumulator layer 1
__device__ float g_h2  [N_NODES * 8];     // (h1 @ W2) * dinv[row], padded 7->8
__device__ float g_agg2[N_NODES * 8];     // scatter accumulator layer 2

// vector atomic add (sm_90+)
__device__ __forceinline__ void red_add_v4(float4* addr, float4 v) {
    asm volatile("red.global.add.v4.f32 [%0], {%1, %2, %3, %4};"
                 :: "l"((float*)addr), "f"(v.x), "f"(v.y), "f"(v.z), "f"(v.w) : "memory");
}

__device__ __forceinline__ void mma_tf32(float* d, const unsigned* a, const unsigned* b) {
    asm volatile(
        "mma.sync.aligned.m16n8k8.row.col.f32.tf32.tf32.f32 "
        "{%0,%1,%2,%3}, {%4,%5,%6,%7}, {%8,%9}, {%0,%1,%2,%3};"
        : "+f"(d[0]), "+f"(d[1]), "+f"(d[2]), "+f"(d[3])
        : "r"(a[0]), "r"(a[1]), "r"(a[2]), "r"(a[3]), "r"(b[0]), "r"(b[1]));
}

__device__ __forceinline__ void cp_async16(void* smem_dst, const void* gsrc, int src_bytes) {
    unsigned saddr = (unsigned)__cvta_generic_to_shared(smem_dst);
    asm volatile("cp.async.cg.shared.global [%0], [%1], 16, %2;"
                 :: "r"(saddr), "l"(gsrc), "r"(src_bytes) : "memory");
}
__device__ __forceinline__ void cp_commit() { asm volatile("cp.async.commit_group;" ::: "memory"); }
__device__ __forceinline__ void cp_wait1()  { asm volatile("cp.async.wait_group 1;" ::: "memory"); }
__device__ __forceinline__ void cp_wait0()  { asm volatile("cp.async.wait_group 0;" ::: "memory"); }

// ---------------- init: zero accumulators, deg=1 (self loop) ----------------
__global__ void init_kernel() {
    int idx = blockIdx.x * blockDim.x + threadIdx.x;
    if (idx < N_NODES * F_H / 4)
        ((float4*)g_agg1)[idx] = make_float4(0.f, 0.f, 0.f, 0.f);
    if (idx < N_NODES * 8 / 4)
        ((float4*)g_agg2)[idx] = make_float4(0.f, 0.f, 0.f, 0.f);
    if (idx < N_NODES)
        g_deg[idx] = 1.0f;   // self-loop contributes 1 to degree
}

// ---------------- degree ----------------
__global__ void deg_kernel(const int* __restrict__ dst, int E) {
    int e = blockIdx.x * blockDim.x + threadIdx.x;
    if (e < E) atomicAdd(&g_deg[dst[e]], 1.0f);
}

__global__ void dinv_kernel() {
    int i = blockIdx.x * blockDim.x + threadIdx.x;
    if (i < N_NODES) g_dinv[i] = rsqrtf(g_deg[i]);
}

// ---------------- GEMM1 (tf32 tensor cores): h = (x @ W1) * dinv ----------------
// M=100000, N=32, K=1433. Block: 128 threads (4 warps). BM=128 rows/block,
// each warp computes 32 rows x 32 cols with m16n8k8 tf32 MMA.
// X rows are only 4B-aligned (stride 5732B = 4 mod 16). We load with 16B
// cp.async from the aligned-down address; row r's data lands shifted by
// sh_r = (global_row & 3) elements in smem. Since row0 % 128 == 0,
// sh_r = r & 3, and every row a given thread reads has shift (gid & 3).
#define BM 128
#define BK 32
#define XPITCH 36
#define WPITCH 40
#define NCHUNK ((F_IN + BK - 1) / BK)   // 45

__global__ __launch_bounds__(128) void gemm1_kernel(
    const float* __restrict__ x, const float* __restrict__ W1)
{
    __shared__ __align__(16) float Xs[2][BM][XPITCH];
    __shared__ __align__(16) float Ws[2][BK][WPITCH];

    const int tid  = threadIdx.x;
    const int lane = tid & 31;
    const int warp = tid >> 5;
    const int gid  = lane >> 2;   // groupID   0..7
    const int tig  = lane & 3;    // thread-in-group 0..3
    const int row0 = blockIdx.x * BM;
    const int sh   = gid & 3;     // smem read shift for this thread's A rows

    float acc[2][4][4];   // [mtile][ntile][reg]
    #pragma unroll
    for (int m = 0; m < 2; ++m)
        #pragma unroll
        for (int n = 0; n < 4; ++n)
            #pragma unroll
            for (int r = 0; r < 4; ++r) acc[m][n][r] = 0.f;

    auto issue_stage = [&](int chunk, int buf) {
        int k0 = chunk * BK;
        // X tile: rows handled by 8 lanes each (8x16B chunks), coalesced.
        #pragma unroll
        for (int i = 0; i < 8; ++i) {
            int r  = i * 16 + (tid >> 3);
            int j0 = (tid & 7) * 4;          // smem element offset, 16B chunk
            int grow = row0 + r;
            const float* srcp = x;
            int valid = 0;
            if (grow < N_NODES) {
                int shift = grow & 3;
                int col = k0 - shift + j0;   // global column of smem slot j0
                int vb = (F_IN - col) * 4;
                valid = vb < 0 ? 0 : (vb > 16 ? 16 : vb);
                srcp = x + ((size_t)grow * F_IN + col);
            }
            cp_async16(&Xs[buf][r][j0], srcp, valid);
        }
        // X tile tail chunk (elements 32..35), needed when shift>0
        {
            int r = tid;
            int grow = row0 + r;
            const float* srcp = x;
            int valid = 0;
            int shift = grow & 3;
            if (grow < N_NODES && shift > 0) {
                int col = k0 - shift + 32;
                int vb = (F_IN - col) * 4;
                valid = vb < 0 ? 0 : (vb > 16 ? 16 : vb);
                srcp = x + ((size_t)grow * F_IN + col);
            }
            cp_async16(&Xs[buf][r][32], srcp, valid);
        }
        // W tile: 32 rows x 32 floats = 256 x 16B chunks, 2 per thread
        #pragma unroll
        for (int i = 0; i < 2; ++i) {
            int lin = i * 128 + tid;
            int kw = lin >> 3;
            int j = lin & 7;
            int gk = k0 + kw;
            int valid = (gk < F_IN) ? 16 : 0;
            const float* srcp = W1 + (size_t)(valid ? gk : 0) * F_H + j * 4;
            cp_async16(&Ws[buf][kw][j * 4], srcp, valid);
        }
    };

    issue_stage(0, 0);
    cp_commit();

    for (int c = 0; c < NCHUNK; ++c) {
        int buf = c & 1;
        bool more = (c + 1 < NCHUNK);
        if (more) { issue_stage(c + 1, buf ^ 1); cp_commit(); }
        if (more) cp_wait1(); else cp_wait0();
        __syncthreads();

        const int wr = warp * 32;
        #pragma unroll
        for (int ks = 0; ks < 4; ++ks) {
            int kb = ks * 8;
            unsigned afr[2][4];
            #pragma unroll
            for (int m = 0; m < 2; ++m) {
                int rb = wr + m * 16;
                afr[m][0] = __float_as_uint(Xs[buf][rb + gid    ][kb + tig + sh    ]);
                afr[m][1] = __float_as_uint(Xs[buf][rb + gid + 8][kb + tig + sh    ]);
                afr[m][2] = __float_as_uint(Xs[buf][rb + gid    ][kb + tig + sh + 4]);
                afr[m][3] = __float_as_uint(Xs[buf][rb + gid + 8][kb + tig + sh + 4]);
            }
            #pragma unroll
            for (int n = 0; n < 4; ++n) {
                unsigned bfr[2];
                bfr[0] = __float_as_uint(Ws[buf][kb + tig    ][n * 8 + gid]);
                bfr[1] = __float_as_uint(Ws[buf][kb + tig + 4][n * 8 + gid]);
                mma_tf32(acc[0][n], afr[0], bfr);
                mma_tf32(acc[1][n], afr[1], bfr);
            }
        }
        __syncthreads();
    }

    // epilogue: scale by dinv[row], store. d0=(r,2t), d1=(r,2t+1), d2/d3=(r+8,..)
    #pragma unroll
    for (int m = 0; m < 2; ++m) {
        int r0r = row0 + warp * 32 + m * 16 + gid;
        int r1r = r0r + 8;
        float w0 = (r0r < N_NODES) ? g_dinv[r0r] : 0.f;
        float w1 = (r1r < N_NODES) ? g_dinv[r1r] : 0.f;
        #pragma unroll
        for (int n = 0; n < 4; ++n) {
            int col = n * 8 + tig * 2;
            if (r0r < N_NODES)
                *(float2*)&g_h[(size_t)r0r * F_H + col] =
                    make_float2(acc[m][n][0] * w0, acc[m][n][1] * w0);
            if (r1r < N_NODES)
                *(float2*)&g_h[(size_t)r1r * F_H + col] =
                    make_float2(acc[m][n][2] * w1, acc[m][n][3] * w1);
        }
    }
}

// ---------------- scatter layer 1: agg1[dst] += h_scaled[src]  (8 thr/edge) ----------------
__global__ __launch_bounds__(256) void scatter1_kernel(
    const int* __restrict__ src, const int* __restrict__ dst, int E)
{
    int t = blockIdx.x * blockDim.x + threadIdx.x;
    int e = t >> 3;
    int q = t & 7;
    if (e >= E) return;
    int s = __ldg(&src[e]);
    int d = __ldg(&dst[e]);
    float4 v = ((const float4*)(g_h + (size_t)s * F_H))[q];
    red_add_v4(((float4*)(g_agg1 + (size_t)d * F_H)) + q, v);
}

// ------- node-wise: h1 = relu(dinv*(agg1+h_s) + b1); h2_s = (h1@W2)*dinv -------
__global__ __launch_bounds__(256) void node1_kernel(
    const float* __restrict__ b1, const float* __restrict__ W2)
{
    __shared__ float sW2[F_H * F_OUT];
    __shared__ float sb1[F_H];
    int tid = threadIdx.x;
    if (tid < F_H * F_OUT) sW2[tid] = W2[tid];
    if (tid < F_H)         sb1[tid] = b1[tid];
    __syncthreads();

    int i = blockIdx.x * blockDim.x + tid;
    if (i >= N_NODES) return;
    float di = g_dinv[i];

    float o[F_OUT];
    #pragma unroll
    for (int c = 0; c < F_OUT; ++c) o[c] = 0.f;

    const float4* ag = (const float4*)(g_agg1 + (size_t)i * F_H);
    const float4* hh = (const float4*)(g_h + (size_t)i * F_H);
    #pragma unroll
    for (int q = 0; q < 8; ++q) {
        float4 a = ag[q];
        float4 h = hh[q];
        float hv[4];
        hv[0] = (a.x + h.x) * di + sb1[q * 4 + 0];
        hv[1] = (a.y + h.y) * di + sb1[q * 4 + 1];
        hv[2] = (a.z + h.z) * di + sb1[q * 4 + 2];
        hv[3] = (a.w + h.w) * di + sb1[q * 4 + 3];
        #pragma unroll
        for (int t = 0; t < 4; ++t) {
            float hr = fmaxf(hv[t], 0.f);
            int j = q * 4 + t;
            #pragma unroll
            for (int c = 0; c < F_OUT; ++c)
                o[c] += hr * sW2[j * F_OUT + c];
        }
    }
    float* out = g_h2 + (size_t)i * 8;
    #pragma unroll
    for (int c = 0; c < F_OUT; ++c) out[c] = o[c] * di;
    out[7] = 0.f;
}

// ---------------- scatter layer 2: agg2[dst] += h2_scaled[src]  (2 thr/edge) ----------------
__global__ __launch_bounds__(256) void scatter2_kernel(
    const int* __restrict__ src, const int* __restrict__ dst, int E)
{
    int t = blockIdx.x * blockDim.x + threadIdx.x;
    int e = t >> 1;
    int q = t & 1;
    if (e >= E) return;
    int s = __ldg(&src[e]);
    int d = __ldg(&dst[e]);
    float4 v = ((const float4*)(g_h2 + (size_t)s * 8))[q];
    red_add_v4(((float4*)(g_agg2 + (size_t)d * 8)) + q, v);
}

// ---------------- final: out = log_softmax(dinv*(agg2+h2_s) + b2) ----------------
__global__ __launch_bounds__(256) void final_kernel(
    const float* __restrict__ b2, float* __restrict__ out)
{
    int i = blockIdx.x * blockDim.x + threadIdx.x;
    if (i >= N_NODES) return;
    float di = g_dinv[i];
    const float* ag = g_agg2 + (size_t)i * 8;
    const float* h2 = g_h2 + (size_t)i * 8;
    float v[F_OUT];
    float m = -1e30f;
    #pragma unroll
    for (int c = 0; c < F_OUT; ++c) {
        v[c] = (ag[c] + h2[c]) * di + b2[c];
        m = fmaxf(m, v[c]);
    }
    float s = 0.f;
    #pragma unroll
    for (int c = 0; c < F_OUT; ++c) s += expf(v[c] - m);
    float lse = m + logf(s);
    float* o = out + (size_t)i * F_OUT;
    #pragma unroll
    for (int c = 0; c < F_OUT; ++c) o[c] = v[c] - lse;
}

// ---------------- launch ----------------
extern "C" void kernel_launch(void* const* d_in, const int* in_sizes, int n_in,
                              void* d_out, int out_size)
{
    const float* x   = (const float*)d_in[0];
    const int*   ei  = (const int*)  d_in[1];
    const float* W1  = (const float*)d_in[2];
    const float* b1  = (const float*)d_in[3];
    const float* W2  = (const float*)d_in[4];
    const float* b2  = (const float*)d_in[5];
    float* out = (float*)d_out;

    const int E = in_sizes[1] / 2;
    const int* src = ei;
    const int* dst = ei + E;

    int nb_init = (N_NODES * F_H / 4 + 255) / 256;
    init_kernel<<<nb_init, 256>>>();

    int nb_e = (E + 255) / 256;
    deg_kernel<<<nb_e, 256>>>(dst, E);

    int nb_n = (N_NODES + 255) / 256;
    dinv_kernel<<<nb_n, 256>>>();

    int nb_g = (N_NODES + BM - 1) / BM;
    gemm1_kernel<<<nb_g, 128>>>(x, W1);

    int nb_s1 = (E * 8 + 255) / 256;
    scatter1_kernel<<<nb_s1, 256>>>(src, dst, E);

    node1_kernel<<<nb_n, 256>>>(b1, W2);

    int nb_s2 = (E * 2 + 255) / 256;
    scatter2_kernel<<<nb_s2, 256>>>(src, dst, E);

    final_kernel<<<nb_n, 256>>>(b2, out);
}